// round 14
// baseline (speedup 1.0000x reference)
#include <cuda_runtime.h>
#include <cuda_bf16.h>
#include <float.h>

// Problem constants
#define BB    4
#define CC    3
#define HH    512
#define WW    512
#define TILE  16
#define RR    8
#define NTH   32          // H / TILE
#define NTW   32          // W / TILE
#define WIN   32          // TILE + 2*R
#define ND    17          // 2*R + 1
#define WPITCH 36         // padded window pitch (floats), 144B: 16B aligned

#define NTHREADS 160      // 5 warps; 153 active compute lanes (95.6% packing)
#define NUNITS   153      // 3 i-thirds x 3 channels x 17 dy

#define NOFF_ELEMS (BB * 2 * NTH * NTW)   // 8192, new_off goes first in d_out

// 2*(w - s) via FFMA-imm (rt_SMSP=1 vs FADD rt=2): d2 = w * 2.0 + ns2, ns2 = -2s.
// Power-of-2 scaling commutes with IEEE rounding: d2 == 2 * fl(w - s) bitwise,
// and the whole accumulation chain is 2x the unscaled one bit-for-bit, so all
// cost comparisons / argmin / tie-breaks are unchanged. ptxas cannot fold
// w*2+c into an FADD, so the imm-form FFMA survives to SASS.
__device__ __forceinline__ float sub2_via_ffma_imm(float w, float ns2)
{
    float d;
    asm("fma.rn.f32 %0, %1, 0f40000000, %2;" : "=f"(d) : "f"(w), "f"(ns2));
    return d;
}

__global__ __launch_bounds__(NTHREADS, 4)
void tile_matching_kernel(const float* __restrict__ src,
                          const float* __restrict__ dst,
                          const int*   __restrict__ offset,
                          float*       __restrict__ out)
{
    const int tileId = blockIdx.x;            // b*1024 + th*32 + tw
    const int b  = tileId >> 10;
    const int th = (tileId >> 5) & 31;
    const int tw = tileId & 31;
    const int t  = threadIdx.x;

    __shared__ float sw[CC][WIN][WPITCH];     // 32x32 window per channel (zero padded OOB)
    __shared__ float ss[CC][TILE][TILE];      // src tile scaled by -2  (-2s)
    __shared__ float part3[3][CC][ND][ND];    // per-(i-third, channel) 2x-scaled costs
    __shared__ float bestC[ND];
    __shared__ int   bestD[ND];
    __shared__ int   s_best;

    // tile offsets (same address across block -> broadcast load)
    const int offy = offset[((b * 2 + 0) * NTH + th) * NTW + tw];
    const int offx = offset[((b * 2 + 1) * NTH + th) * NTW + tw];

    const int ti = th * TILE;
    const int tj = tw * TILE;

    // ---- Load 3x32x32 window from dst (zero for OOB == reference's zero padding) ----
    for (int idx = t; idx < CC * WIN * WIN; idx += NTHREADS) {
        const int c  = idx >> 10;             // /1024
        const int wy = (idx >> 5) & 31;
        const int wx = idx & 31;
        const int gy = ti + offy - RR + wy;
        const int gx = tj + offx - RR + wx;
        float v = 0.0f;
        if (gy >= 0 && gy < HH && gx >= 0 && gx < WW)
            v = dst[((b * CC + c) * HH + gy) * WW + gx];
        sw[c][wy][wx] = v;
    }
    // ---- Load 3x16x16 src tile, scaled by -2 (exact) ----
    for (int idx = t; idx < CC * TILE * TILE; idx += NTHREADS) {
        const int c = idx >> 8;
        const int i = (idx >> 4) & 15;
        const int j = idx & 15;
        ss[c][i][j] = -2.0f * src[((b * CC + c) * HH + ti + i) * WW + tj + j];
    }
    __syncthreads();

    // ---- SAD over 17x17 candidates (2x-scaled costs; argmin invariant).
    // Unit u = third*51 + c*17 + dy, u < 153. i-ranges {0..5},{6..10},{11..15};
    // third = u/51 keeps each warp i-range-homogeneous.
    // Per pixel: FFMA-imm (1 fma-cyc) + FADD |.| (2 fma-cyc) = 3 fma-cyc,
    // vs 4 for the FADD+FADD baseline. 17 independent chains -> issue-bound.
    if (t < NUNITS) {
        const int third = t / 51;
        const int r     = t - third * 51;
        const int c     = r / ND;
        const int dy    = r - c * ND;
        const int i0    = (third == 0) ? 0 : (third == 1 ? 6 : 11);
        const int ni    = (third == 0) ? 6 : 5;

        float acc[ND];
#pragma unroll
        for (int dx = 0; dx < ND; ++dx) acc[dx] = 0.0f;

        for (int ii = 0; ii < ni; ++ii) {
            const int i = i0 + ii;
            // window row (dy+i): 32 floats via 8x LDS.128 (row base 16B aligned)
            float w[WIN];
            {
                const float4* wr = reinterpret_cast<const float4*>(&sw[c][dy + i][0]);
#pragma unroll
                for (int k = 0; k < 8; ++k) {
                    float4 v = wr[k];
                    w[4 * k + 0] = v.x; w[4 * k + 1] = v.y;
                    w[4 * k + 2] = v.z; w[4 * k + 3] = v.w;
                }
            }
            // -2s row i: 16 floats (broadcast among lanes sharing (c,i))
            float s[TILE];
            {
                const float4* sr = reinterpret_cast<const float4*>(&ss[c][i][0]);
#pragma unroll
                for (int k = 0; k < 4; ++k) {
                    float4 v = sr[k];
                    s[4 * k + 0] = v.x; s[4 * k + 1] = v.y;
                    s[4 * k + 2] = v.z; s[4 * k + 3] = v.w;
                }
            }
#pragma unroll
            for (int dx = 0; dx < ND; ++dx) {
#pragma unroll
                for (int j = 0; j < TILE; ++j) {
                    const float d = sub2_via_ffma_imm(w[dx + j], s[j]);  // 2*(w-s)
                    acc[dx] += fabsf(d);    // FADD with |.| source modifier
                }
            }
        }
#pragma unroll
        for (int dx = 0; dx < ND; ++dx) part3[third][c][dy][dx] = acc[dx];
    }
    __syncthreads();

    // ---- reduce (thirds, channels) + argmin over dx per dy.
    // Fixed order; ascending dx with strict '<' keeps the FIRST minimum,
    // matching the reference scan's (cost < best_c) update over ascending d.
    // (All costs share the exact 2x scale -> identical comparisons.)
    if (t < ND) {
        const int dy = t;
        float bc = FLT_MAX;
        int   bd = 0;
        for (int dx = 0; dx < ND; ++dx) {
            const float c0 = part3[0][0][dy][dx] + part3[1][0][dy][dx] + part3[2][0][dy][dx];
            const float c1 = part3[0][1][dy][dx] + part3[1][1][dy][dx] + part3[2][1][dy][dx];
            const float c2 = part3[0][2][dy][dx] + part3[1][2][dy][dx] + part3[2][2][dy][dx];
            const float cst = c0 + c1 + c2;
            const int d = dy * ND + dx;
            if (cst < bc) { bc = cst; bd = d; }
        }
        bestC[dy] = bc;
        bestD[dy] = bd;
    }
    __syncthreads();

    // ---- final argmin over dy: lexicographic (cost, d) => smallest d on exact tie ----
    if (t == 0) {
        float bc = bestC[0];
        int   bd = bestD[0];
        for (int k = 1; k < ND; ++k) {
            if (bestC[k] < bc || (bestC[k] == bc && bestD[k] < bd)) {
                bc = bestC[k];
                bd = bestD[k];
            }
        }
        s_best = bd;
        const int dy_ = bd / ND - RR;
        const int dx_ = bd % ND - RR;
        out[((b * 2 + 0) * NTH + th) * NTW + tw] = (float)(offy + dy_);
        out[((b * 2 + 1) * NTH + th) * NTW + tw] = (float)(offx + dx_);
    }
    __syncthreads();

    // ---- write aligned tile: sub-window [wy0..wy0+15][wx0..wx0+15] of sw ----
    const int bd  = s_best;
    const int wy0 = bd / ND;    // dy_ + R
    const int wx0 = bd % ND;    // dx_ + R
    for (int idx = t; idx < CC * TILE * TILE; idx += NTHREADS) {
        const int c = idx >> 8;
        const int i = (idx >> 4) & 15;
        const int j = idx & 15;
        out[NOFF_ELEMS + ((b * CC + c) * HH + ti + i) * WW + tj + j] =
            sw[c][wy0 + i][wx0 + j];
    }
}

extern "C" void kernel_launch(void* const* d_in, const int* in_sizes, int n_in,
                              void* d_out, int out_size)
{
    const float* src    = (const float*)d_in[0];
    const float* dst    = (const float*)d_in[1];
    const int*   offset = (const int*)d_in[2];
    float*       out    = (float*)d_out;

    dim3 grid(BB * NTH * NTW);   // 4096 tiles
    dim3 block(NTHREADS);
    tile_matching_kernel<<<grid, block>>>(src, dst, offset, out);
}

// round 15
// speedup vs baseline: 1.5331x; 1.5331x over previous
#include <cuda_runtime.h>
#include <cuda_bf16.h>
#include <float.h>

// Problem constants
#define BB    4
#define CC    3
#define HH    512
#define WW    512
#define TILE  16
#define RR    8
#define NTH   32          // H / TILE
#define NTW   32          // W / TILE
#define WIN   32          // TILE + 2*R
#define ND    17          // 2*R + 1
#define WPITCH 36         // padded window pitch (floats), 144B: 16B aligned

#define NTHREADS 160      // 5 warps; 153 active compute lanes (95.6% packing)
#define NUNITS   153      // 3 i-thirds x 3 channels x 17 dy

#define NOFF_ELEMS (BB * 2 * NTH * NTW)   // 8192, new_off goes first in d_out

__global__ __launch_bounds__(NTHREADS, 4)
void tile_matching_kernel(const float* __restrict__ src,
                          const float* __restrict__ dst,
                          const int*   __restrict__ offset,
                          float*       __restrict__ out)
{
    const int tileId = blockIdx.x;            // b*1024 + th*32 + tw
    const int b  = tileId >> 10;
    const int th = (tileId >> 5) & 31;
    const int tw = tileId & 31;
    const int t  = threadIdx.x;

    __shared__ float sw[CC][WIN][WPITCH];     // 32x32 window per channel (zero padded OOB)
    __shared__ float ss[CC][TILE][TILE];      // src tile scaled by -2  (ns2 = -2s)
    __shared__ float part3[3][CC][ND][ND];    // per-(i-third, channel) 4x-scaled costs
    __shared__ float bestC[ND];
    __shared__ int   bestD[ND];
    __shared__ int   s_best;

    // tile offsets (same address across block -> broadcast load)
    const int offy = offset[((b * 2 + 0) * NTH + th) * NTW + tw];
    const int offx = offset[((b * 2 + 1) * NTH + th) * NTW + tw];

    const int ti = th * TILE;
    const int tj = tw * TILE;

    // ---- Load 3x32x32 window from dst (zero for OOB == reference's zero padding) ----
    for (int idx = t; idx < CC * WIN * WIN; idx += NTHREADS) {
        const int c  = idx >> 10;             // /1024
        const int wy = (idx >> 5) & 31;
        const int wx = idx & 31;
        const int gy = ti + offy - RR + wy;
        const int gx = tj + offx - RR + wx;
        float v = 0.0f;
        if (gy >= 0 && gy < HH && gx >= 0 && gx < WW)
            v = dst[((b * CC + c) * HH + gy) * WW + gx];
        sw[c][wy][wx] = v;
    }
    // ---- Load 3x16x16 src tile, scaled by -2 (exact power-of-2) ----
    for (int idx = t; idx < CC * TILE * TILE; idx += NTHREADS) {
        const int c = idx >> 8;
        const int i = (idx >> 4) & 15;
        const int j = idx & 15;
        ss[c][i][j] = -2.0f * src[((b * CC + c) * HH + ti + i) * WW + tj + j];
    }
    __syncthreads();

    // ---- SAD over 17x17 candidates (4x-scaled costs; argmin bitwise-invariant).
    // Unit u = third*51 + c*17 + dy, u < 153. i-ranges {0..5},{6..10},{11..15};
    // third = u/51 keeps each warp i-range-homogeneous.
    //
    // Per pixel (both FFMA src1-imm form, rt_SMSP=1 -> 2 fma-cyc total vs 4):
    //   d2  = fmaf(w, 2.0f, -2s)        == 2*fl(w-s)   (exact 2x, single round)
    //   acc = fmaf(|d2|, 2.0f, acc)     adds 4*|w-s|, single round
    // Power-of-2 scaling commutes with IEEE rounding, so every partial sum is
    // exactly 4x the unscaled FADD chain -> identical comparisons/tie-breaks.
    if (t < NUNITS) {
        const int third = t / 51;
        const int r     = t - third * 51;
        const int c     = r / ND;
        const int dy    = r - c * ND;
        const int i0    = (third == 0) ? 0 : (third == 1 ? 6 : 11);
        const int ni    = (third == 0) ? 6 : 5;

        float acc[ND];
#pragma unroll
        for (int dx = 0; dx < ND; ++dx) acc[dx] = 0.0f;

        for (int ii = 0; ii < ni; ++ii) {
            const int i = i0 + ii;
            // window row (dy+i): 32 floats via 8x LDS.128 (row base 16B aligned)
            float w[WIN];
            {
                const float4* wr = reinterpret_cast<const float4*>(&sw[c][dy + i][0]);
#pragma unroll
                for (int k = 0; k < 8; ++k) {
                    float4 v = wr[k];
                    w[4 * k + 0] = v.x; w[4 * k + 1] = v.y;
                    w[4 * k + 2] = v.z; w[4 * k + 3] = v.w;
                }
            }
            // ns2 = -2s row i: 16 floats (broadcast among lanes sharing (c,i))
            float s[TILE];
            {
                const float4* sr = reinterpret_cast<const float4*>(&ss[c][i][0]);
#pragma unroll
                for (int k = 0; k < 4; ++k) {
                    float4 v = sr[k];
                    s[4 * k + 0] = v.x; s[4 * k + 1] = v.y;
                    s[4 * k + 2] = v.z; s[4 * k + 3] = v.w;
                }
            }
#pragma unroll
            for (int dx = 0; dx < ND; ++dx) {
#pragma unroll
                for (int j = 0; j < TILE; ++j) {
                    const float d2 = fmaf(w[dx + j], 2.0f, s[j]);   // FFMA-imm
                    acc[dx] = fmaf(fabsf(d2), 2.0f, acc[dx]);       // FFMA-imm, |.| folded
                }
            }
        }
#pragma unroll
        for (int dx = 0; dx < ND; ++dx) part3[third][c][dy][dx] = acc[dx];
    }
    __syncthreads();

    // ---- reduce (thirds, channels) + argmin over dx per dy.
    // Fixed order; ascending dx with strict '<' keeps the FIRST minimum,
    // matching the reference scan's (cost < best_c) update over ascending d.
    // (All costs share the exact 4x scale -> identical comparisons.)
    if (t < ND) {
        const int dy = t;
        float bc = FLT_MAX;
        int   bd = 0;
        for (int dx = 0; dx < ND; ++dx) {
            const float c0 = part3[0][0][dy][dx] + part3[1][0][dy][dx] + part3[2][0][dy][dx];
            const float c1 = part3[0][1][dy][dx] + part3[1][1][dy][dx] + part3[2][1][dy][dx];
            const float c2 = part3[0][2][dy][dx] + part3[1][2][dy][dx] + part3[2][2][dy][dx];
            const float cst = c0 + c1 + c2;
            const int d = dy * ND + dx;
            if (cst < bc) { bc = cst; bd = d; }
        }
        bestC[dy] = bc;
        bestD[dy] = bd;
    }
    __syncthreads();

    // ---- final argmin over dy: lexicographic (cost, d) => smallest d on exact tie ----
    if (t == 0) {
        float bc = bestC[0];
        int   bd = bestD[0];
        for (int k = 1; k < ND; ++k) {
            if (bestC[k] < bc || (bestC[k] == bc && bestD[k] < bd)) {
                bc = bestC[k];
                bd = bestD[k];
            }
        }
        s_best = bd;
        const int dy_ = bd / ND - RR;
        const int dx_ = bd % ND - RR;
        out[((b * 2 + 0) * NTH + th) * NTW + tw] = (float)(offy + dy_);
        out[((b * 2 + 1) * NTH + th) * NTW + tw] = (float)(offx + dx_);
    }
    __syncthreads();

    // ---- write aligned tile: sub-window [wy0..wy0+15][wx0..wx0+15] of sw ----
    const int bd  = s_best;
    const int wy0 = bd / ND;    // dy_ + R
    const int wx0 = bd % ND;    // dx_ + R
    for (int idx = t; idx < CC * TILE * TILE; idx += NTHREADS) {
        const int c = idx >> 8;
        const int i = (idx >> 4) & 15;
        const int j = idx & 15;
        out[NOFF_ELEMS + ((b * CC + c) * HH + ti + i) * WW + tj + j] =
            sw[c][wy0 + i][wx0 + j];
    }
}

extern "C" void kernel_launch(void* const* d_in, const int* in_sizes, int n_in,
                              void* d_out, int out_size)
{
    const float* src    = (const float*)d_in[0];
    const float* dst    = (const float*)d_in[1];
    const int*   offset = (const int*)d_in[2];
    float*       out    = (float*)d_out;

    dim3 grid(BB * NTH * NTW);   // 4096 tiles
    dim3 block(NTHREADS);
    tile_matching_kernel<<<grid, block>>>(src, dst, offset, out);
}

// round 17
// speedup vs baseline: 1.5878x; 1.0357x over previous
#include <cuda_runtime.h>
#include <cuda_bf16.h>
#include <float.h>

// Problem constants
#define BB    4
#define CC    3
#define HH    512
#define WW    512
#define TILE  16
#define RR    8
#define NTH   32          // H / TILE
#define NTW   32          // W / TILE
#define WIN   32          // TILE + 2*R
#define ND    17          // 2*R + 1
#define WPITCH 36         // padded window pitch (floats), 144B: 16B aligned

#define NTHREADS 160      // 5 warps; 153 active compute lanes (95.6% packing)
#define NUNITS   153      // 3 i-thirds x 3 channels x 17 dy

#define NOFF_ELEMS (BB * 2 * NTH * NTW)   // 8192, new_off goes first in d_out

__global__ __launch_bounds__(NTHREADS, 4)
void tile_matching_kernel(const float* __restrict__ src,
                          const float* __restrict__ dst,
                          const int*   __restrict__ offset,
                          float*       __restrict__ out)
{
    const int tileId = blockIdx.x;            // b*1024 + th*32 + tw
    const int b  = tileId >> 10;
    const int th = (tileId >> 5) & 31;
    const int tw = tileId & 31;
    const int t  = threadIdx.x;

    __shared__ float sw[CC][WIN][WPITCH];     // 32x32 window per channel (zero padded OOB)
    __shared__ float ss[CC][TILE][TILE];      // src tile
    __shared__ float part3[3][CC][ND][ND];    // per-(i-third, channel) candidate costs
    __shared__ float bestC[ND];
    __shared__ int   bestD[ND];
    __shared__ int   s_best;

    // tile offsets (same address across block -> broadcast load)
    const int offy = offset[((b * 2 + 0) * NTH + th) * NTW + tw];
    const int offx = offset[((b * 2 + 1) * NTH + th) * NTW + tw];

    const int ti = th * TILE;
    const int tj = tw * TILE;

    const int gy0 = ti + offy - RR;           // window top-left in image coords
    const int gx0 = tj + offx - RR;

    // ---- Load 3x32x32 window from dst ----
    // Interior fast path (~88% of tiles): whole 32x32 window in-bounds ->
    // unconditional loads, no per-element clamp. Loads identical values to the
    // guarded path, so everything downstream is bitwise identical.
    if (gy0 >= 0 && gy0 + WIN <= HH && gx0 >= 0 && gx0 + WIN <= WW) {
        const float* dbase = dst + gy0 * WW + gx0;   // + c*HH*WW + wy*WW + wx
        for (int idx = t; idx < CC * WIN * WIN; idx += NTHREADS) {
            const int c  = idx >> 10;             // /1024
            const int wy = (idx >> 5) & 31;
            const int wx = idx & 31;
            sw[c][wy][wx] = dbase[(b * CC + c) * (HH * WW) + wy * WW + wx];
        }
    } else {
        // Border path: zero for OOB == reference's zero padding.
        for (int idx = t; idx < CC * WIN * WIN; idx += NTHREADS) {
            const int c  = idx >> 10;
            const int wy = (idx >> 5) & 31;
            const int wx = idx & 31;
            const int gy = gy0 + wy;
            const int gx = gx0 + wx;
            float v = 0.0f;
            if (gy >= 0 && gy < HH && gx >= 0 && gx < WW)
                v = dst[((b * CC + c) * HH + gy) * WW + gx];
            sw[c][wy][wx] = v;
        }
    }
    // ---- Load 3x16x16 src tile (always in-bounds) ----
    for (int idx = t; idx < CC * TILE * TILE; idx += NTHREADS) {
        const int c = idx >> 8;
        const int i = (idx >> 4) & 15;
        const int j = idx & 15;
        ss[c][i][j] = src[((b * CC + c) * HH + ti + i) * WW + tj + j];
    }
    __syncthreads();

    // ---- SAD over 17x17 candidates.
    // Unit u = third*51 + c*17 + dy, u < 153. i-ranges {0..5},{6..10},{11..15};
    // third = u/51 keeps each warp i-range-homogeneous.
    // Per pixel: FADD (w-s) + FADD acc += |d| (abs = free source modifier).
    // 17 independent chains -> fma-issue-bound, not latency-bound.
    if (t < NUNITS) {
        const int third = t / 51;
        const int r     = t - third * 51;
        const int c     = r / ND;
        const int dy    = r - c * ND;
        const int i0    = (third == 0) ? 0 : (third == 1 ? 6 : 11);
        const int ni    = (third == 0) ? 6 : 5;

        float acc[ND];
#pragma unroll
        for (int dx = 0; dx < ND; ++dx) acc[dx] = 0.0f;

        for (int ii = 0; ii < ni; ++ii) {
            const int i = i0 + ii;
            // window row (dy+i): 32 floats via 8x LDS.128 (row base 16B aligned)
            float w[WIN];
            {
                const float4* wr = reinterpret_cast<const float4*>(&sw[c][dy + i][0]);
#pragma unroll
                for (int k = 0; k < 8; ++k) {
                    float4 v = wr[k];
                    w[4 * k + 0] = v.x; w[4 * k + 1] = v.y;
                    w[4 * k + 2] = v.z; w[4 * k + 3] = v.w;
                }
            }
            // src row i: 16 floats (broadcast among lanes sharing (c,i))
            float s[TILE];
            {
                const float4* sr = reinterpret_cast<const float4*>(&ss[c][i][0]);
#pragma unroll
                for (int k = 0; k < 4; ++k) {
                    float4 v = sr[k];
                    s[4 * k + 0] = v.x; s[4 * k + 1] = v.y;
                    s[4 * k + 2] = v.z; s[4 * k + 3] = v.w;
                }
            }
#pragma unroll
            for (int dx = 0; dx < ND; ++dx) {
#pragma unroll
                for (int j = 0; j < TILE; ++j) {
                    acc[dx] += fabsf(w[dx + j] - s[j]);   // FADD with |.| modifier
                }
            }
        }
#pragma unroll
        for (int dx = 0; dx < ND; ++dx) part3[third][c][dy][dx] = acc[dx];
    }
    __syncthreads();

    // ---- reduce (thirds, channels) + argmin over dx per dy.
    // Fixed order; ascending dx with strict '<' keeps the FIRST minimum,
    // matching the reference scan's (cost < best_c) update over ascending d.
    if (t < ND) {
        const int dy = t;
        float bc = FLT_MAX;
        int   bd = 0;
        for (int dx = 0; dx < ND; ++dx) {
            const float c0 = part3[0][0][dy][dx] + part3[1][0][dy][dx] + part3[2][0][dy][dx];
            const float c1 = part3[0][1][dy][dx] + part3[1][1][dy][dx] + part3[2][1][dy][dx];
            const float c2 = part3[0][2][dy][dx] + part3[1][2][dy][dx] + part3[2][2][dy][dx];
            const float cst = c0 + c1 + c2;
            const int d = dy * ND + dx;
            if (cst < bc) { bc = cst; bd = d; }
        }
        bestC[dy] = bc;
        bestD[dy] = bd;
    }
    __syncthreads();

    // ---- final argmin over dy: lexicographic (cost, d) => smallest d on exact tie ----
    if (t == 0) {
        float bc = bestC[0];
        int   bd = bestD[0];
        for (int k = 1; k < ND; ++k) {
            if (bestC[k] < bc || (bestC[k] == bc && bestD[k] < bd)) {
                bc = bestC[k];
                bd = bestD[k];
            }
        }
        s_best = bd;
        const int dy_ = bd / ND - RR;
        const int dx_ = bd % ND - RR;
        out[((b * 2 + 0) * NTH + th) * NTW + tw] = (float)(offy + dy_);
        out[((b * 2 + 1) * NTH + th) * NTW + tw] = (float)(offx + dx_);
    }
    __syncthreads();

    // ---- write aligned tile: sub-window [wy0..wy0+15][wx0..wx0+15] of sw ----
    const int bd  = s_best;
    const int wy0 = bd / ND;    // dy_ + R
    const int wx0 = bd % ND;    // dx_ + R
    for (int idx = t; idx < CC * TILE * TILE; idx += NTHREADS) {
        const int c = idx >> 8;
        const int i = (idx >> 4) & 15;
        const int j = idx & 15;
        out[NOFF_ELEMS + ((b * CC + c) * HH + ti + i) * WW + tj + j] =
            sw[c][wy0 + i][wx0 + j];
    }
}

extern "C" void kernel_launch(void* const* d_in, const int* in_sizes, int n_in,
                              void* d_out, int out_size)
{
    const float* src    = (const float*)d_in[0];
    const float* dst    = (const float*)d_in[1];
    const int*   offset = (const int*)d_in[2];
    float*       out    = (float*)d_out;

    dim3 grid(BB * NTH * NTW);   // 4096 tiles
    dim3 block(NTHREADS);
    tile_matching_kernel<<<grid, block>>>(src, dst, offset, out);
}